// round 10
// baseline (speedup 1.0000x reference)
#include <cuda_runtime.h>
#include <cstdint>

#define NUM_HEADS 8
#define IN_BITS   64
#define N_STATE   256
#define N_OUT     64
#define K_CONN    8
#define HASH      65536
#define BATCH     128
#define T_STEPS   128
#define TOTAL_IN  320   // IN_BITS + N_STATE

// Bit-packed threshold table: bit = (state_mem[n][a] >= 0.5). 2 MB, L2-resident.
__device__ uint32_t g_state_bits[N_STATE * (HASH / 32)];

// ---------------------------------------------------------------------------
// Prologue: pack state_mem (64 MB floats) into g_state_bits (2 MB). HBM-bound.
// ---------------------------------------------------------------------------
__global__ void pack_state_mem_kernel(const float* __restrict__ sm)
{
    const int tid  = blockIdx.x * blockDim.x + threadIdx.x;
    const int lane = threadIdx.x & 31;
    const int gw   = tid >> 5;
    const size_t base = (size_t)gw * 128;
    #pragma unroll
    for (int j = 0; j < 4; j++) {
        float v = sm[base + (size_t)j * 32 + lane];
        uint32_t b = __ballot_sync(0xFFFFFFFFu, v >= 0.5f);
        if (lane == 0) g_state_bits[gw * 4 + j] = b;
    }
}

// ---------------------------------------------------------------------------
// Main scan. One CTA per batch, 256 threads, thread t = neuron t.
// Warp-class stagger: class A (warps 0-3) issues [state dot -> LDG] first so
// its 128 L1tex wavefronts drain while class B (warps 4-7) is still issuing
// its dp2a stream (B does next-step window dot BEFORE the state dot). A's
// gather returns land during bar1's wait; B consumes its word after bar1.
// Per SMSP the two resident warps (w, w+4) are in the SAME class -> whole
// SMSPs are staggered, creating real drain/issue overlap.
// ---------------------------------------------------------------------------
__global__ __launch_bounds__(256, 1)
void ram_scan_kernel(const int*   __restrict__ bits,          // (B, T*64)
                     const int*   __restrict__ state_coeffs,  // (256, 320)
                     const int*   __restrict__ head_conn,     // (8, 64, 8)
                     const int*   __restrict__ head_coeffs,   // (8, 64, 8)
                     const float* __restrict__ head_mem,      // (8, 64, 65536)
                     float*       __restrict__ out)           // (B, 64)
{
    __shared__ uint32_t win_words[T_STEPS * 16]; // 8 KB: all window bits as bytes
    __shared__ uint32_t stbuf[2][64];            // double-buffered 256 state bytes

    const int b = blockIdx.x;
    const int t = threadIdx.x;                   // neuron id

    // ---- expand all T windows to 0/1 bytes ----
    const int4* bits4 = reinterpret_cast<const int4*>(bits + (size_t)b * (T_STEPS * IN_BITS));
    for (int w = t; w < T_STEPS * 16; w += 256) {
        int4 v = bits4[w];
        win_words[w] = (uint32_t)(v.x & 1) | ((uint32_t)(v.y & 1) << 8)
                     | ((uint32_t)(v.z & 1) << 16) | ((uint32_t)(v.w & 1) << 24);
    }
    if (t < 64) stbuf[0][t] = 0u;   // initial state = 0

    // ---- coefficients as u16 pairs for dp2a (exact u32 accumulation) ----
    uint32_t w2[32], c2[128];
    {
        const int4* crow = reinterpret_cast<const int4*>(state_coeffs + (size_t)t * TOTAL_IN);
        #pragma unroll
        for (int k = 0; k < 16; k++) {
            int4 v = crow[k];
            w2[2*k]   = (uint32_t)(v.x & 0xFFFF) | ((uint32_t)v.y << 16);
            w2[2*k+1] = (uint32_t)(v.z & 0xFFFF) | ((uint32_t)v.w << 16);
        }
        #pragma unroll
        for (int k = 0; k < 64; k++) {
            int4 v = crow[16 + k];
            c2[2*k]   = (uint32_t)(v.x & 0xFFFF) | ((uint32_t)v.y << 16);
            c2[2*k+1] = (uint32_t)(v.z & 0xFFFF) | ((uint32_t)v.w << 16);
        }
    }
    __syncthreads();   // win_words + stbuf[0] ready

    const uint4* wv = reinterpret_cast<const uint4*>(win_words); // 4 uint4 / step

    #define WIN_ACC(STEP, OUTV)                                                 \
    {                                                                           \
        uint32_t _a0 = 0u, _a1 = 0u, _a2 = 0u, _a3 = 0u;                        \
        _Pragma("unroll")                                                       \
        for (int q = 0; q < 4; q++) {                                           \
            uint4 x = wv[(STEP) * 4 + q];                                       \
            _a0 = __dp2a_lo(w2[8*q+0], x.x, _a0); _a0 = __dp2a_hi(w2[8*q+1], x.x, _a0); \
            _a1 = __dp2a_lo(w2[8*q+2], x.y, _a1); _a1 = __dp2a_hi(w2[8*q+3], x.y, _a1); \
            _a2 = __dp2a_lo(w2[8*q+4], x.z, _a2); _a2 = __dp2a_hi(w2[8*q+5], x.z, _a2); \
            _a3 = __dp2a_lo(w2[8*q+6], x.w, _a3); _a3 = __dp2a_hi(w2[8*q+7], x.w, _a3); \
        }                                                                       \
        (OUTV) = (_a0 + _a1) + (_a2 + _a3);                                     \
    }

    // full state dot: 128 dp2a over 16 uint4
    #define STATE_DOT(BUF, OUTV)                                                \
    {                                                                           \
        const uint4* _s4 = reinterpret_cast<const uint4*>(BUF);                 \
        uint32_t _a0 = 0u, _a1 = 0u, _a2 = 0u, _a3 = 0u;                        \
        _Pragma("unroll")                                                       \
        for (int q = 0; q < 16; q++) {                                          \
            uint4 x = _s4[q];                                                   \
            _a0 = __dp2a_lo(c2[8*q+0], x.x, _a0); _a0 = __dp2a_hi(c2[8*q+1], x.x, _a0); \
            _a1 = __dp2a_lo(c2[8*q+2], x.y, _a1); _a1 = __dp2a_hi(c2[8*q+3], x.y, _a1); \
            _a2 = __dp2a_lo(c2[8*q+4], x.z, _a2); _a2 = __dp2a_hi(c2[8*q+5], x.z, _a2); \
            _a3 = __dp2a_lo(c2[8*q+6], x.w, _a3); _a3 = __dp2a_hi(c2[8*q+7], x.w, _a3); \
        }                                                                       \
        (OUTV) = (_a0 + _a1) + (_a2 + _a3);                                     \
    }

    const uint32_t* prow = g_state_bits + ((size_t)t << 11);   // 2048 words/row

    uint32_t wacc;
    WIN_ACC(0, wacc);

    const bool classA = (t < 128);

    #pragma unroll 2
    for (int step = 0; step < T_STEPS; step++) {
        const int cur = step & 1, nxt = cur ^ 1;
        const int stepn = (step + 1) & (T_STEPS - 1);
        uint8_t* stn = reinterpret_cast<uint8_t*>(stbuf[nxt]);

        uint32_t d, wnext, addr, wword;
        if (classA) {
            // A: state dot ASAP -> gather issues early -> drain overlaps B's issue
            STATE_DOT(stbuf[cur], d);
            addr  = (d + wacc) & 0xFFFFu;
            wword = __ldg(prow + (addr >> 5));
            WIN_ACC(stepn, wnext);                  // fills A's post-LDG wait
            stn[t] = (uint8_t)((wword >> (addr & 31u)) & 1u);
        } else {
            // B: window dot first (delays B's gather past A's drain window)
            WIN_ACC(stepn, wnext);
            STATE_DOT(stbuf[cur], d);
            addr  = (d + wacc) & 0xFFFFu;
            wword = __ldg(prow + (addr >> 5));
        }
        __syncthreads();   // bar1: A's bytes visible; B arrived right after LDG
        if (!classA)       // B's word returned during bar1 wait
            stn[t] = (uint8_t)((wword >> (addr & 31u)) & 1u);
        __syncthreads();   // bar2: full next state visible; old buffer free
        wacc = wnext;
    }

    // ---- Head readout (threads 0..63); T even -> final state in stbuf[0] ----
    if (t < N_OUT) {
        const uint8_t* state_b = reinterpret_cast<const uint8_t*>(stbuf[0]);
        const int* lw = bits + (size_t)b * (T_STEPS * IN_BITS) + (T_STEPS * IN_BITS - 3);
        const int hidx = (lw[0] << 2) + (lw[1] << 1) + lw[2];    // 0..7
        const int o    = t;
        const int base = (hidx * N_OUT + o) * K_CONN;
        uint32_t addr = 0u;
        #pragma unroll
        for (int k = 0; k < K_CONN; k++) {
            int conn = __ldg(head_conn + base + k);
            uint32_t c = (uint32_t)__ldg(head_coeffs + base + k);
            addr += state_b[conn] ? c : 0u;
        }
        addr &= 0xFFFFu;
        out[(size_t)b * N_OUT + o] =
            __ldg(head_mem + (((size_t)(hidx * N_OUT + o)) << 16) + addr);
    }
    #undef WIN_ACC
    #undef STATE_DOT
}

extern "C" void kernel_launch(void* const* d_in, const int* in_sizes, int n_in,
                              void* d_out, int out_size)
{
    const int*   bits         = (const int*)  d_in[0];
    const int*   state_coeffs = (const int*)  d_in[1];
    const float* state_mem    = (const float*)d_in[2];
    const int*   head_conn    = (const int*)  d_in[3];
    const int*   head_coeffs  = (const int*)  d_in[4];
    const float* head_mem     = (const float*)d_in[5];
    float*       out          = (float*)      d_out;

    pack_state_mem_kernel<<<16384, 256>>>(state_mem);
    ram_scan_kernel<<<BATCH, 256>>>(bits, state_coeffs,
                                    head_conn, head_coeffs, head_mem, out);
}